// round 16
// baseline (speedup 1.0000x reference)
#include <cuda_runtime.h>
#include <cuda_bf16.h>
#include <cuda_fp16.h>
#include <cstdint>

// Problem constants
#define DIMC 1024
#define Hc   16
#define KVc  8
#define HDc  64
#define Bc   8
#define Pc   1024
#define MROWS (Bc * Pc)   // 8192
#define KD   1024
#define NQKV 2048         // Q(1024) + K(512) + V(512)

typedef unsigned long long u64;

// ---------------------------------------------------------------------------
// mma.sync / ldmatrix / cp.async helpers (baseline PTX only)
// ---------------------------------------------------------------------------
__device__ __forceinline__ uint32_t smem_u32(const void* p) {
    uint32_t a;
    asm("{ .reg .u64 t; cvta.to.shared.u64 t, %1; cvt.u32.u64 %0, t; }" : "=r"(a) : "l"(p));
    return a;
}
__device__ __forceinline__ void ldm_x4(uint32_t* r, uint32_t addr) {
    asm volatile("ldmatrix.sync.aligned.m8n8.x4.shared.b16 {%0,%1,%2,%3}, [%4];"
                 : "=r"(r[0]), "=r"(r[1]), "=r"(r[2]), "=r"(r[3]) : "r"(addr));
}
__device__ __forceinline__ void ldm_x4t(uint32_t* r, uint32_t addr) {
    asm volatile("ldmatrix.sync.aligned.m8n8.x4.trans.shared.b16 {%0,%1,%2,%3}, [%4];"
                 : "=r"(r[0]), "=r"(r[1]), "=r"(r[2]), "=r"(r[3]) : "r"(addr));
}
__device__ __forceinline__ void ldm_x2(uint32_t* r, uint32_t addr) {
    asm volatile("ldmatrix.sync.aligned.m8n8.x2.shared.b16 {%0,%1}, [%2];"
                 : "=r"(r[0]), "=r"(r[1]) : "r"(addr));
}
__device__ __forceinline__ void mma_f16(float* d, const uint32_t* a, const uint32_t* b) {
    asm volatile(
        "mma.sync.aligned.m16n8k16.row.col.f32.f16.f16.f32 "
        "{%0,%1,%2,%3}, {%4,%5,%6,%7}, {%8,%9}, {%0,%1,%2,%3};"
        : "+f"(d[0]), "+f"(d[1]), "+f"(d[2]), "+f"(d[3])
        : "r"(a[0]), "r"(a[1]), "r"(a[2]), "r"(a[3]), "r"(b[0]), "r"(b[1]));
}
#define CP_ASYNC16(dst, src) \
    asm volatile("cp.async.cg.shared.global [%0], [%1], 16;" :: "r"(dst), "l"(src))
#define CP_COMMIT()  asm volatile("cp.async.commit_group;" ::: "memory")
#define CP_WAIT1()   asm volatile("cp.async.wait_group 1;" ::: "memory")
#define CP_WAIT0()   asm volatile("cp.async.wait_group 0;" ::: "memory")

// p_pair = 2^(s_hi, s_lo) as packed fp16x2 (low half = s_lo's result)
__device__ __forceinline__ uint32_t exp2_h2(float s_hi, float s_lo) {
    uint32_t t;
    asm("cvt.rn.f16x2.f32 %0, %1, %2;" : "=r"(t) : "f"(s_hi), "f"(s_lo));
    asm("ex2.approx.f16x2 %0, %0;" : "+r"(t));
    return t;
}

// ---------------------------------------------------------------------------
// Scratch (device globals; allocation-free)
// ---------------------------------------------------------------------------
#define KN_SPLIT 8
__device__ float g_norm2p[Bc * KVc * KN_SPLIT];
__device__ int   g_kvidx[Hc];
__device__ __half g_Xf[(size_t)MROWS * KD];   // fp16 activations (QKV GEMM A)
__device__ __half g_Wf[(size_t)NQKV * KD];    // fp16 Wq|Wk|Wv (QKV GEMM B)
__device__ __half g_Pf[(size_t)DIMC * KD];    // fp16 Wp (proj GEMM B)
__device__ __half g_Of[(size_t)MROWS * KD];   // fp16 attn output (proj GEMM A)
__device__ __half g_Qf[(size_t)Bc * Hc * Pc * HDc];   // fp16 Q (scaled log2e/8)
__device__ __half g_Kf[(size_t)Bc * KVc * Pc * HDc];  // fp16 K
__device__ __half g_Vf[(size_t)Bc * KVc * Pc * HDc];  // fp16 V

// ---------------------------------------------------------------------------
// fp32 -> fp16 converts
// ---------------------------------------------------------------------------
__global__ __launch_bounds__(256) void convert_f16(const float* __restrict__ src,
                                                   __half* __restrict__ dst, int n) {
    int i = (blockIdx.x * 256 + threadIdx.x) * 4;
    if (i >= n) return;
    float4 v = *(const float4*)(src + i);
    *(__half2*)(dst + i)     = __floats2half2_rn(v.x, v.y);
    *(__half2*)(dst + i + 2) = __floats2half2_rn(v.z, v.w);
}

// One launch for all four weight tensors.
__global__ __launch_bounds__(256) void convert_weights(
    const float* __restrict__ Wq, const float* __restrict__ Wk,
    const float* __restrict__ Wv, const float* __restrict__ Wp)
{
    const int blk = blockIdx.x;
    const float* src;
    __half* dst;
    int off;
    if (blk < 1024)      { src = Wq; dst = g_Wf;                       off = blk; }
    else if (blk < 1536) { src = Wk; dst = g_Wf + (size_t)1024 * KD;   off = blk - 1024; }
    else if (blk < 2048) { src = Wv; dst = g_Wf + (size_t)1536 * KD;   off = blk - 1536; }
    else                 { src = Wp; dst = g_Pf;                       off = blk - 2048; }
    const int i = off * 1024 + threadIdx.x * 4;
    float4 v = *(const float4*)(src + i);
    *(__half2*)(dst + i)     = __floats2half2_rn(v.x, v.y);
    *(__half2*)(dst + i + 2) = __floats2half2_rn(v.z, v.w);
}

// ---------------------------------------------------------------------------
// QKV epilogue: Q/K/V as fp16 (Q scaled by log2e/8 for ex2 softmax)
// ---------------------------------------------------------------------------
#define QSCALE 0.1803368801111204f   // 0.125 * log2(e)
__device__ __forceinline__ void store_qkv2(int m, int n, float vx, float vy) {
    const int bb = m >> 10;
    const int p  = m & 1023;
    if (n < 1024) {
        const int hh = n >> 6, d = n & 63;
        *(__half2*)&g_Qf[(((size_t)bb * Hc + hh) * Pc + p) * HDc + d] =
            __floats2half2_rn(vx * QSCALE, vy * QSCALE);
    } else if (n < 1536) {
        const int kvh = (n - 1024) >> 6, d = n & 63;
        *(__half2*)&g_Kf[(((size_t)bb * KVc + kvh) * Pc + p) * HDc + d] =
            __floats2half2_rn(vx, vy);
    } else {
        const int kvh = (n - 1536) >> 6, d = n & 63;
        *(__half2*)&g_Vf[(((size_t)bb * KVc + kvh) * Pc + p) * HDc + d] =
            __floats2half2_rn(vx, vy);
    }
}

// ---------------------------------------------------------------------------
// fp16 single-product GEMM: C[m,n] = sum_k A[m,k] * B[n,k]. (R15, passing)
// ---------------------------------------------------------------------------
#define LDT 40
#define TILE_B (128 * LDT * 2)          // 10240 bytes per tile
#define GBUF (2 * TILE_B)               // A + B
#define SMEM_G16 (2 * GBUF)             // 40960

__global__ __launch_bounds__(256) void gemm_f16(
    const __half* __restrict__ A_g, const __half* __restrict__ B_g,
    const float* __restrict__ bias, float* __restrict__ out, int mode)
{
    extern __shared__ char smem[];
    const uint32_t sb = smem_u32(smem);
    const int tid = threadIdx.x;
    const int wid = tid >> 5, lane = tid & 31;
    const int wm = wid >> 2, wn = wid & 3;
    const int gid = lane >> 2, tig = lane & 3;
    const int m0 = blockIdx.y * 128;
    const int n0 = blockIdx.x * 128;

    const __half* srcs[2] = { A_g + (size_t)m0 * KD, B_g + (size_t)n0 * KD };

    const int r0 = tid >> 2, c0 = (tid & 3) * 8;
    const int r1 = r0 + 64;
    const int rA = lane & 15;
    const int kA = ((lane >> 4) << 3);
    const int rB = lane & 7;
    const int kB = (((lane >> 3) & 1) << 3);

    float acc[4][4][4];
#pragma unroll
    for (int i = 0; i < 4; i++)
#pragma unroll
        for (int j = 0; j < 4; j++)
#pragma unroll
            for (int c = 0; c < 4; c++) acc[i][j][c] = 0.f;

#pragma unroll
    for (int t = 0; t < 2; ++t) {
        CP_ASYNC16(sb + t * TILE_B + (r0 * LDT + c0) * 2, srcs[t] + (size_t)r0 * KD + c0);
        CP_ASYNC16(sb + t * TILE_B + (r1 * LDT + c0) * 2, srcs[t] + (size_t)r1 * KD + c0);
    }
    CP_COMMIT();

    const int NC = KD / 32;
    for (int kc = 0; kc < NC; ++kc) {
        const uint32_t buf = sb + (kc & 1) * GBUF;
        if (kc + 1 < NC) {
            const uint32_t nb = sb + ((kc + 1) & 1) * GBUF;
            const int koff = (kc + 1) * 32;
#pragma unroll
            for (int t = 0; t < 2; ++t) {
                CP_ASYNC16(nb + t * TILE_B + (r0 * LDT + c0) * 2, srcs[t] + (size_t)r0 * KD + koff + c0);
                CP_ASYNC16(nb + t * TILE_B + (r1 * LDT + c0) * 2, srcs[t] + (size_t)r1 * KD + koff + c0);
            }
            CP_COMMIT();
            CP_WAIT1();
        } else {
            CP_WAIT0();
        }
        __syncthreads();

        const uint32_t sA = buf, sB = buf + TILE_B;
#pragma unroll
        for (int s = 0; s < 2; ++s) {
            uint32_t a4[4][4];
#pragma unroll
            for (int mt = 0; mt < 4; ++mt)
                ldm_x4(a4[mt], sA + ((wm * 64 + mt * 16 + rA) * LDT + s * 16 + kA) * 2);
#pragma unroll
            for (int nt = 0; nt < 4; ++nt) {
                uint32_t b2[2];
                ldm_x2(b2, sB + ((wn * 32 + nt * 8 + rB) * LDT + s * 16 + kB) * 2);
#pragma unroll
                for (int mt = 0; mt < 4; ++mt)
                    mma_f16(acc[mt][nt], a4[mt], b2);
            }
        }
        __syncthreads();
    }

#pragma unroll
    for (int mt = 0; mt < 4; ++mt) {
#pragma unroll
        for (int nt = 0; nt < 4; ++nt) {
            const int mg = m0 + wm * 64 + mt * 16 + gid;
            const int n  = n0 + wn * 32 + nt * 8 + tig * 2;
            float* a = acc[mt][nt];
            if (mode == 0) {
                store_qkv2(mg,     n, a[0], a[1]);
                store_qkv2(mg + 8, n, a[2], a[3]);
            } else {
                const float2 bb = *(const float2*)&bias[n];
                *(float2*)&out[(size_t)mg * DIMC + n] = make_float2(a[0] + bb.x, a[1] + bb.y);
                *(float2*)&out[(size_t)(mg + 8) * DIMC + n] = make_float2(a[2] + bb.x, a[3] + bb.y);
            }
        }
    }
}

// ---------------------------------------------------------------------------
// K norm^2 partials: 512 blocks, each covers 1/8 of a (b,kv) slice.
// Deterministic (no atomics); alloc_kernel sums the 8 partials.
// ---------------------------------------------------------------------------
__global__ void knorm_kernel() {
    const int bk = blockIdx.x >> 3;          // 0..63
    const int sub = blockIdx.x & 7;          // 0..7
    const int n2 = Pc * HDc / 2;             // 32768 half2 per slice
    const int seg = n2 / KN_SPLIT;           // 4096
    const __half2* K2 = (const __half2*)(g_Kf + (size_t)bk * Pc * HDc) + sub * seg;
    float s = 0.f;
    for (int i = threadIdx.x; i < seg; i += blockDim.x) {
        float2 v = __half22float2(K2[i]);
        s += v.x * v.x + v.y * v.y;
    }
#pragma unroll
    for (int off = 16; off >= 1; off >>= 1)
        s += __shfl_xor_sync(0xffffffffu, s, off);
    __shared__ float red[8];
    const int wid = threadIdx.x >> 5, lid = threadIdx.x & 31;
    if (lid == 0) red[wid] = s;
    __syncthreads();
    if (threadIdx.x == 0) {
        float t = 0.f;
        for (int w = 0; w < (int)(blockDim.x >> 5); ++w) t += red[w];
        g_norm2p[bk * KN_SPLIT + sub] = t;
    }
}

// ---------------------------------------------------------------------------
// Head allocation (sums knorm partials deterministically)
// ---------------------------------------------------------------------------
__global__ void alloc_kernel() {
    if (threadIdx.x != 0) return;
    float kn[KVc];
    for (int kv = 0; kv < KVc; ++kv) {
        float s = 0.f;
        for (int b = 0; b < Bc; ++b) {
            float n2 = 0.f;
            for (int q = 0; q < KN_SPLIT; ++q)
                n2 += g_norm2p[(b * KVc + kv) * KN_SPLIT + q];
            s += sqrtf(n2);
        }
        kn[kv] = s;
    }
    float mn = kn[0], mx = kn[0];
    for (int kv = 1; kv < KVc; ++kv) { mn = fminf(mn, kn[kv]); mx = fmaxf(mx, kn[kv]); }
    float sum = 0.f;
    for (int kv = 0; kv < KVc; ++kv) { kn[kv] = (kn[kv] - mn) / (mx - mn); sum += kn[kv]; }
    int alloc[KVc]; int tot = 0;
    for (int kv = 0; kv < KVc; ++kv) {
        alloc[kv] = (int)rintf(kn[kv] / sum * (float)Hc);
        tot += alloc[kv];
    }
    while (tot > Hc) {
        int am = 0;
        for (int i = 1; i < KVc; ++i) if (alloc[i] > alloc[am]) am = i;
        alloc[am]--; tot--;
    }
    while (tot < Hc) {
        int am = 0;
        for (int i = 1; i < KVc; ++i) if (alloc[i] < alloc[am]) am = i;
        alloc[am]++; tot++;
    }
    int cum[KVc]; int c = 0;
    for (int kv = 0; kv < KVc; ++kv) { c += alloc[kv]; cum[kv] = c; }
    for (int h = 0; h < Hc; ++h) {
        int i = 0;
        while (cum[i] <= h) i++;
        g_kvidx[h] = i;
    }
}

// ---------------------------------------------------------------------------
// fp16 tensor-core flash attention; QK restructured ntp-major so the score
// block (16 regs) converts to P fragments immediately — cuts peak register
// liveness ~48 regs to fit the occupancy-3 cap without spills.
// Arithmetic identical to R15 (same mma order per accumulator).
// ---------------------------------------------------------------------------
#define FPB  144
#define TILE_H (64 * FPB)
#define BUFH (2 * TILE_H)
#define SMEM_FLASH (2 * BUFH)
#define ONES_H2 0x3C003C00u

__global__ __launch_bounds__(128, 3) void flash_mma() {
    extern __shared__ char fsm[];
    const uint32_t sb = smem_u32(fsm);
    const int tid = threadIdx.x;
    const int w = tid >> 5, lane = tid & 31;
    const int gid = lane >> 2, tig = lane & 3;

    const int bh = blockIdx.y;
    const int b = bh >> 4, h = bh & 15;
    const int kv = g_kvidx[h];
    const int q0 = blockIdx.x * 128;

    const __half* Qf = g_Qf + ((size_t)(b * Hc + h) * Pc + q0) * HDc;
    const __half* Kf = g_Kf + (size_t)(b * KVc + kv) * Pc * HDc;
    const __half* Vf = g_Vf + (size_t)(b * KVc + kv) * Pc * HDc;

    const int lr = tid >> 1;
    const int lcb = (tid & 1) * 64;

    auto load_kv = [&](int chunk, uint32_t dst) {
        const size_t go = (size_t)(chunk * 64 + lr) * (HDc * 2) + lcb;
        const uint32_t so = dst + lr * FPB + lcb;
#pragma unroll
        for (int j = 0; j < 4; ++j) {
            CP_ASYNC16(so + j * 16,          (const char*)Kf + go + j * 16);
            CP_ASYNC16(so + TILE_H + j * 16, (const char*)Vf + go + j * 16);
        }
    };

    {
        const size_t go = (size_t)tid * (HDc * 2);
        const uint32_t so = sb + BUFH + tid * FPB;
#pragma unroll
        for (int j = 0; j < 8; ++j)
            CP_ASYNC16(so + j * 16, (const char*)Qf + go + j * 16);
    }
    CP_COMMIT();            // g0: Q
    load_kv(0, sb);
    CP_COMMIT();            // g1: KV0
    CP_WAIT1();             // Q ready
    __syncthreads();

    uint32_t ah[2][4][4];
#pragma unroll
    for (int mt = 0; mt < 2; ++mt)
#pragma unroll
        for (int ks = 0; ks < 4; ++ks) {
            const uint32_t aq = sb + BUFH + (w * 32 + mt * 16 + (lane & 15)) * FPB
                                + (ks * 16 + ((lane >> 4) & 1) * 8) * 2;
            ldm_x4(ah[mt][ks], aq);
        }
    __syncthreads();
    load_kv(1, sb + BUFH);
    CP_COMMIT();            // g2: KV1

    const uint32_t b_ones[2] = { ONES_H2, ONES_H2 };
    float lacc[2][4];
    float o[2][8][4];
#pragma unroll
    for (int mt = 0; mt < 2; ++mt) {
#pragma unroll
        for (int c = 0; c < 4; c++) lacc[mt][c] = 0.f;
#pragma unroll
        for (int i = 0; i < 8; i++)
#pragma unroll
            for (int c = 0; c < 4; c++) o[mt][i][c] = 0.f;
    }

    for (int kt = 0; kt < Pc / 64; ++kt) {
        CP_WAIT1();
        __syncthreads();
        const uint32_t buf = sb + (kt & 1) * BUFH;

        // ---- S' and P per key-group (ntp-major: 16-reg score block, then exp) ----
        uint32_t pa[2][4][4];
#pragma unroll
        for (int ntp = 0; ntp < 4; ++ntp) {
            float sl[2][2][4];
#pragma unroll
            for (int mt = 0; mt < 2; ++mt)
#pragma unroll
                for (int i = 0; i < 2; ++i)
#pragma unroll
                    for (int c = 0; c < 4; ++c) sl[mt][i][c] = 0.f;

#pragma unroll
            for (int ks = 0; ks < 4; ++ks) {
                uint32_t k4[4];
                const uint32_t ab = buf
                    + (ntp * 16 + ((lane >> 4) << 3) + (lane & 7)) * FPB
                    + (ks * 16 + ((lane >> 3) & 1) * 8) * 2;
                ldm_x4(k4, ab);
#pragma unroll
                for (int mt = 0; mt < 2; ++mt) {
                    mma_f16(sl[mt][0], ah[mt][ks], k4);
                    mma_f16(sl[mt][1], ah[mt][ks], k4 + 2);
                }
            }
#pragma unroll
            for (int mt = 0; mt < 2; ++mt) {
                pa[mt][ntp][0] = exp2_h2(sl[mt][0][1], sl[mt][0][0]);
                pa[mt][ntp][1] = exp2_h2(sl[mt][0][3], sl[mt][0][2]);
                pa[mt][ntp][2] = exp2_h2(sl[mt][1][1], sl[mt][1][0]);
                pa[mt][ntp][3] = exp2_h2(sl[mt][1][3], sl[mt][1][2]);
            }
        }

        // ---- l += P @ ones ----
#pragma unroll
        for (int mt = 0; mt < 2; ++mt)
#pragma unroll
            for (int kks = 0; kks < 4; ++kks)
                mma_f16(lacc[mt], pa[mt][kks], b_ones);

        // ---- O += P V ----
#pragma unroll
        for (int kks = 0; kks < 4; ++kks) {
#pragma unroll
            for (int dtp = 0; dtp < 4; ++dtp) {
                uint32_t v4[4];
                const uint32_t av = buf + TILE_H
                    + (kks * 16 + ((lane >> 3) & 1) * 8 + (lane & 7)) * FPB
                    + (dtp * 16 + ((lane >> 4) & 1) * 8) * 2;
                ldm_x4t(v4, av);
#pragma unroll
                for (int mt = 0; mt < 2; ++mt) {
                    mma_f16(o[mt][dtp * 2],     pa[mt][kks], v4);
                    mma_f16(o[mt][dtp * 2 + 1], pa[mt][kks], v4 + 2);
                }
            }
        }
        __syncthreads();
        if (kt + 2 < Pc / 64) {
            load_kv(kt + 2, sb + (kt & 1) * BUFH);
            CP_COMMIT();
        }
    }

    // ---- epilogue: normalize, write fp16 into proj-GEMM A (g_Of) ----
#pragma unroll
    for (int mt = 0; mt < 2; ++mt) {
        const float inv0 = 1.f / lacc[mt][0], inv1 = 1.f / lacc[mt][2];
        const size_t rowbase = (size_t)(b * Pc + q0 + w * 32 + mt * 16);
#pragma unroll
        for (int dt = 0; dt < 8; ++dt) {
            const int col = h * HDc + dt * 8 + tig * 2;
            *(__half2*)&g_Of[(rowbase + gid) * DIMC + col] =
                __floats2half2_rn(o[mt][dt][0] * inv0, o[mt][dt][1] * inv0);
            *(__half2*)&g_Of[(rowbase + gid + 8) * DIMC + col] =
                __floats2half2_rn(o[mt][dt][2] * inv1, o[mt][dt][3] * inv1);
        }
    }
}

// ---------------------------------------------------------------------------
extern "C" void kernel_launch(void* const* d_in, const int* in_sizes, int n_in,
                              void* d_out, int out_size) {
    const float* x  = (const float*)d_in[0];
    const float* Wq = (const float*)d_in[1];
    const float* Wk = (const float*)d_in[2];
    const float* Wv = (const float*)d_in[3];
    const float* Wp = (const float*)d_in[4];
    const float* bp = (const float*)d_in[5];
    float* out = (float*)d_out;

    static bool init_done = false;
    static __half *pXf, *pWf, *pPf, *pOf;
    if (!init_done) {
        cudaFuncSetAttribute(gemm_f16, cudaFuncAttributeMaxDynamicSharedMemorySize, SMEM_G16);
        cudaFuncSetAttribute(flash_mma, cudaFuncAttributeMaxDynamicSharedMemorySize, SMEM_FLASH);
        cudaGetSymbolAddress((void**)&pXf, g_Xf);
        cudaGetSymbolAddress((void**)&pWf, g_Wf);
        cudaGetSymbolAddress((void**)&pPf, g_Pf);
        cudaGetSymbolAddress((void**)&pOf, g_Of);
        init_done = true;
    }

    // converts: x (one launch) + all four weight tensors (one launch)
    convert_f16<<<MROWS * KD / 1024, 256>>>(x, pXf, MROWS * KD);
    convert_weights<<<3072, 256>>>(Wq, Wk, Wv, Wp);

    // QKV projection (fp16 single-product) -> fp16 Q/K/V
    gemm_f16<<<dim3(NQKV / 128, MROWS / 128), 256, SMEM_G16>>>(
        pXf, pWf, nullptr, nullptr, 0);

    knorm_kernel<<<Bc * KVc * KN_SPLIT, 256>>>();
    alloc_kernel<<<1, 32>>>();

    // fp16 tensor-core flash attention -> fp16 attn output into g_Of
    flash_mma<<<dim3(Pc / 128, Bc * Hc), 128, SMEM_FLASH>>>();

    // output projection (fp16 single-product) + bias -> fp32 out
    gemm_f16<<<dim3(DIMC / 128, MROWS / 128), 256, SMEM_G16>>>(
        pOf, pPf, bp, out, 1);
}

// round 17
// speedup vs baseline: 1.0208x; 1.0208x over previous
#include <cuda_runtime.h>
#include <cuda_bf16.h>
#include <cuda_fp16.h>
#include <cstdint>

// Problem constants
#define DIMC 1024
#define Hc   16
#define KVc  8
#define HDc  64
#define Bc   8
#define Pc   1024
#define MROWS (Bc * Pc)   // 8192
#define KD   1024
#define NQKV 2048         // Q(1024) + K(512) + V(512)

typedef unsigned long long u64;

// ---------------------------------------------------------------------------
// mma.sync / ldmatrix / cp.async helpers (baseline PTX only)
// ---------------------------------------------------------------------------
__device__ __forceinline__ uint32_t smem_u32(const void* p) {
    uint32_t a;
    asm("{ .reg .u64 t; cvta.to.shared.u64 t, %1; cvt.u32.u64 %0, t; }" : "=r"(a) : "l"(p));
    return a;
}
__device__ __forceinline__ void ldm_x4(uint32_t* r, uint32_t addr) {
    asm volatile("ldmatrix.sync.aligned.m8n8.x4.shared.b16 {%0,%1,%2,%3}, [%4];"
                 : "=r"(r[0]), "=r"(r[1]), "=r"(r[2]), "=r"(r[3]) : "r"(addr));
}
__device__ __forceinline__ void ldm_x4t(uint32_t* r, uint32_t addr) {
    asm volatile("ldmatrix.sync.aligned.m8n8.x4.trans.shared.b16 {%0,%1,%2,%3}, [%4];"
                 : "=r"(r[0]), "=r"(r[1]), "=r"(r[2]), "=r"(r[3]) : "r"(addr));
}
__device__ __forceinline__ void ldm_x2(uint32_t* r, uint32_t addr) {
    asm volatile("ldmatrix.sync.aligned.m8n8.x2.shared.b16 {%0,%1}, [%2];"
                 : "=r"(r[0]), "=r"(r[1]) : "r"(addr));
}
__device__ __forceinline__ void mma_f16(float* d, const uint32_t* a, const uint32_t* b) {
    asm volatile(
        "mma.sync.aligned.m16n8k16.row.col.f32.f16.f16.f32 "
        "{%0,%1,%2,%3}, {%4,%5,%6,%7}, {%8,%9}, {%0,%1,%2,%3};"
        : "+f"(d[0]), "+f"(d[1]), "+f"(d[2]), "+f"(d[3])
        : "r"(a[0]), "r"(a[1]), "r"(a[2]), "r"(a[3]), "r"(b[0]), "r"(b[1]));
}
#define CP_ASYNC16(dst, src) \
    asm volatile("cp.async.cg.shared.global [%0], [%1], 16;" :: "r"(dst), "l"(src))
#define CP_COMMIT()  asm volatile("cp.async.commit_group;" ::: "memory")
#define CP_WAIT1()   asm volatile("cp.async.wait_group 1;" ::: "memory")
#define CP_WAIT0()   asm volatile("cp.async.wait_group 0;" ::: "memory")

// p_pair = 2^(s_hi, s_lo) as packed fp16x2 (low half = s_lo's result)
__device__ __forceinline__ uint32_t exp2_h2(float s_hi, float s_lo) {
    uint32_t t;
    asm("cvt.rn.f16x2.f32 %0, %1, %2;" : "=r"(t) : "f"(s_hi), "f"(s_lo));
    asm("ex2.approx.f16x2 %0, %0;" : "+r"(t));
    return t;
}

// ---------------------------------------------------------------------------
// Scratch (device globals; allocation-free)
// ---------------------------------------------------------------------------
#define KN_SPLIT 8
__device__ float g_norm2p[Bc * KVc * KN_SPLIT];
__device__ int   g_kvidx[Hc];
__device__ __half g_Xf[(size_t)MROWS * KD];   // fp16 activations (QKV GEMM A)
__device__ __half g_Wf[(size_t)NQKV * KD];    // fp16 Wq|Wk|Wv (QKV GEMM B)
__device__ __half g_Pf[(size_t)DIMC * KD];    // fp16 Wp (proj GEMM B)
__device__ __half g_Of[(size_t)MROWS * KD];   // fp16 attn output (proj GEMM A)
__device__ __half g_Qf[(size_t)Bc * Hc * Pc * HDc];   // fp16 Q (scaled log2e/8)
__device__ __half g_Kf[(size_t)Bc * KVc * Pc * HDc];  // fp16 K
__device__ __half g_Vf[(size_t)Bc * KVc * Pc * HDc];  // fp16 V

// ---------------------------------------------------------------------------
// fp32 -> fp16 converts
// ---------------------------------------------------------------------------
__global__ __launch_bounds__(256) void convert_f16(const float* __restrict__ src,
                                                   __half* __restrict__ dst, int n) {
    int i = (blockIdx.x * 256 + threadIdx.x) * 4;
    if (i >= n) return;
    float4 v = *(const float4*)(src + i);
    *(__half2*)(dst + i)     = __floats2half2_rn(v.x, v.y);
    *(__half2*)(dst + i + 2) = __floats2half2_rn(v.z, v.w);
}

// One launch for all four weight tensors.
__global__ __launch_bounds__(256) void convert_weights(
    const float* __restrict__ Wq, const float* __restrict__ Wk,
    const float* __restrict__ Wv, const float* __restrict__ Wp)
{
    const int blk = blockIdx.x;
    const float* src;
    __half* dst;
    int off;
    if (blk < 1024)      { src = Wq; dst = g_Wf;                       off = blk; }
    else if (blk < 1536) { src = Wk; dst = g_Wf + (size_t)1024 * KD;   off = blk - 1024; }
    else if (blk < 2048) { src = Wv; dst = g_Wf + (size_t)1536 * KD;   off = blk - 1536; }
    else                 { src = Wp; dst = g_Pf;                       off = blk - 2048; }
    const int i = off * 1024 + threadIdx.x * 4;
    float4 v = *(const float4*)(src + i);
    *(__half2*)(dst + i)     = __floats2half2_rn(v.x, v.y);
    *(__half2*)(dst + i + 2) = __floats2half2_rn(v.z, v.w);
}

// ---------------------------------------------------------------------------
// QKV epilogue: Q/K/V as fp16 (Q scaled by log2e/8 for ex2 softmax)
// ---------------------------------------------------------------------------
#define QSCALE 0.1803368801111204f   // 0.125 * log2(e)
__device__ __forceinline__ void store_qkv2(int m, int n, float vx, float vy) {
    const int bb = m >> 10;
    const int p  = m & 1023;
    if (n < 1024) {
        const int hh = n >> 6, d = n & 63;
        *(__half2*)&g_Qf[(((size_t)bb * Hc + hh) * Pc + p) * HDc + d] =
            __floats2half2_rn(vx * QSCALE, vy * QSCALE);
    } else if (n < 1536) {
        const int kvh = (n - 1024) >> 6, d = n & 63;
        *(__half2*)&g_Kf[(((size_t)bb * KVc + kvh) * Pc + p) * HDc + d] =
            __floats2half2_rn(vx, vy);
    } else {
        const int kvh = (n - 1536) >> 6, d = n & 63;
        *(__half2*)&g_Vf[(((size_t)bb * KVc + kvh) * Pc + p) * HDc + d] =
            __floats2half2_rn(vx, vy);
    }
}

// ---------------------------------------------------------------------------
// fp16 single-product GEMM: C[m,n] = sum_k A[m,k] * B[n,k]. (R15, passing)
// ---------------------------------------------------------------------------
#define LDT 40
#define TILE_B (128 * LDT * 2)          // 10240 bytes per tile
#define GBUF (2 * TILE_B)               // A + B
#define SMEM_G16 (2 * GBUF)             // 40960

__global__ __launch_bounds__(256) void gemm_f16(
    const __half* __restrict__ A_g, const __half* __restrict__ B_g,
    const float* __restrict__ bias, float* __restrict__ out, int mode)
{
    extern __shared__ char smem[];
    const uint32_t sb = smem_u32(smem);
    const int tid = threadIdx.x;
    const int wid = tid >> 5, lane = tid & 31;
    const int wm = wid >> 2, wn = wid & 3;
    const int gid = lane >> 2, tig = lane & 3;
    const int m0 = blockIdx.y * 128;
    const int n0 = blockIdx.x * 128;

    const __half* srcs[2] = { A_g + (size_t)m0 * KD, B_g + (size_t)n0 * KD };

    const int r0 = tid >> 2, c0 = (tid & 3) * 8;
    const int r1 = r0 + 64;
    const int rA = lane & 15;
    const int kA = ((lane >> 4) << 3);
    const int rB = lane & 7;
    const int kB = (((lane >> 3) & 1) << 3);

    float acc[4][4][4];
#pragma unroll
    for (int i = 0; i < 4; i++)
#pragma unroll
        for (int j = 0; j < 4; j++)
#pragma unroll
            for (int c = 0; c < 4; c++) acc[i][j][c] = 0.f;

#pragma unroll
    for (int t = 0; t < 2; ++t) {
        CP_ASYNC16(sb + t * TILE_B + (r0 * LDT + c0) * 2, srcs[t] + (size_t)r0 * KD + c0);
        CP_ASYNC16(sb + t * TILE_B + (r1 * LDT + c0) * 2, srcs[t] + (size_t)r1 * KD + c0);
    }
    CP_COMMIT();

    const int NC = KD / 32;
    for (int kc = 0; kc < NC; ++kc) {
        const uint32_t buf = sb + (kc & 1) * GBUF;
        if (kc + 1 < NC) {
            const uint32_t nb = sb + ((kc + 1) & 1) * GBUF;
            const int koff = (kc + 1) * 32;
#pragma unroll
            for (int t = 0; t < 2; ++t) {
                CP_ASYNC16(nb + t * TILE_B + (r0 * LDT + c0) * 2, srcs[t] + (size_t)r0 * KD + koff + c0);
                CP_ASYNC16(nb + t * TILE_B + (r1 * LDT + c0) * 2, srcs[t] + (size_t)r1 * KD + koff + c0);
            }
            CP_COMMIT();
            CP_WAIT1();
        } else {
            CP_WAIT0();
        }
        __syncthreads();

        const uint32_t sA = buf, sB = buf + TILE_B;
#pragma unroll
        for (int s = 0; s < 2; ++s) {
            uint32_t a4[4][4];
#pragma unroll
            for (int mt = 0; mt < 4; ++mt)
                ldm_x4(a4[mt], sA + ((wm * 64 + mt * 16 + rA) * LDT + s * 16 + kA) * 2);
#pragma unroll
            for (int nt = 0; nt < 4; ++nt) {
                uint32_t b2[2];
                ldm_x2(b2, sB + ((wn * 32 + nt * 8 + rB) * LDT + s * 16 + kB) * 2);
#pragma unroll
                for (int mt = 0; mt < 4; ++mt)
                    mma_f16(acc[mt][nt], a4[mt], b2);
            }
        }
        __syncthreads();
    }

#pragma unroll
    for (int mt = 0; mt < 4; ++mt) {
#pragma unroll
        for (int nt = 0; nt < 4; ++nt) {
            const int mg = m0 + wm * 64 + mt * 16 + gid;
            const int n  = n0 + wn * 32 + nt * 8 + tig * 2;
            float* a = acc[mt][nt];
            if (mode == 0) {
                store_qkv2(mg,     n, a[0], a[1]);
                store_qkv2(mg + 8, n, a[2], a[3]);
            } else {
                const float2 bb = *(const float2*)&bias[n];
                *(float2*)&out[(size_t)mg * DIMC + n] = make_float2(a[0] + bb.x, a[1] + bb.y);
                *(float2*)&out[(size_t)(mg + 8) * DIMC + n] = make_float2(a[2] + bb.x, a[3] + bb.y);
            }
        }
    }
}

// ---------------------------------------------------------------------------
// K norm^2 partials: 512 blocks (R16, passing)
// ---------------------------------------------------------------------------
__global__ void knorm_kernel() {
    const int bk = blockIdx.x >> 3;
    const int sub = blockIdx.x & 7;
    const int n2 = Pc * HDc / 2;
    const int seg = n2 / KN_SPLIT;
    const __half2* K2 = (const __half2*)(g_Kf + (size_t)bk * Pc * HDc) + sub * seg;
    float s = 0.f;
    for (int i = threadIdx.x; i < seg; i += blockDim.x) {
        float2 v = __half22float2(K2[i]);
        s += v.x * v.x + v.y * v.y;
    }
#pragma unroll
    for (int off = 16; off >= 1; off >>= 1)
        s += __shfl_xor_sync(0xffffffffu, s, off);
    __shared__ float red[8];
    const int wid = threadIdx.x >> 5, lid = threadIdx.x & 31;
    if (lid == 0) red[wid] = s;
    __syncthreads();
    if (threadIdx.x == 0) {
        float t = 0.f;
        for (int w = 0; w < (int)(blockDim.x >> 5); ++w) t += red[w];
        g_norm2p[bk * KN_SPLIT + sub] = t;
    }
}

// ---------------------------------------------------------------------------
// Head allocation (sums knorm partials deterministically)
// ---------------------------------------------------------------------------
__global__ void alloc_kernel() {
    if (threadIdx.x != 0) return;
    float kn[KVc];
    for (int kv = 0; kv < KVc; ++kv) {
        float s = 0.f;
        for (int b = 0; b < Bc; ++b) {
            float n2 = 0.f;
            for (int q = 0; q < KN_SPLIT; ++q)
                n2 += g_norm2p[(b * KVc + kv) * KN_SPLIT + q];
            s += sqrtf(n2);
        }
        kn[kv] = s;
    }
    float mn = kn[0], mx = kn[0];
    for (int kv = 1; kv < KVc; ++kv) { mn = fminf(mn, kn[kv]); mx = fmaxf(mx, kn[kv]); }
    float sum = 0.f;
    for (int kv = 0; kv < KVc; ++kv) { kn[kv] = (kn[kv] - mn) / (mx - mn); sum += kn[kv]; }
    int alloc[KVc]; int tot = 0;
    for (int kv = 0; kv < KVc; ++kv) {
        alloc[kv] = (int)rintf(kn[kv] / sum * (float)Hc);
        tot += alloc[kv];
    }
    while (tot > Hc) {
        int am = 0;
        for (int i = 1; i < KVc; ++i) if (alloc[i] > alloc[am]) am = i;
        alloc[am]--; tot--;
    }
    while (tot < Hc) {
        int am = 0;
        for (int i = 1; i < KVc; ++i) if (alloc[i] < alloc[am]) am = i;
        alloc[am]++; tot++;
    }
    int cum[KVc]; int c = 0;
    for (int kv = 0; kv < KVc; ++kv) { c += alloc[kv]; cum[kv] = c; }
    for (int h = 0; h < Hc; ++h) {
        int i = 0;
        while (cum[i] <= h) i++;
        g_kvidx[h] = i;
    }
}

// ---------------------------------------------------------------------------
// fp16 flash attention: 256 q-rows/block, 8 warps, occ 2 (16 warps/SM).
// Per-key-group fused pipeline: QK -> exp -> l-mma -> PV, so P fragments die
// within each group (low register liveness). KV L2 traffic halved vs 128-row
// tiles. Accumulation order per accumulator identical to R16.
// ---------------------------------------------------------------------------
#define FPB  144
#define TILE_H (64 * FPB)           // 9216
#define BUFH (2 * TILE_H)           // 18432 (K + V)
#define SMEM_FLASH (2 * BUFH)       // 36864 (also exactly holds Q 256xFPB)
#define ONES_H2 0x3C003C00u

__global__ __launch_bounds__(256, 2) void flash_mma() {
    extern __shared__ char fsm[];
    const uint32_t sb = smem_u32(fsm);
    const int tid = threadIdx.x;
    const int w = tid >> 5, lane = tid & 31;
    const int gid = lane >> 2, tig = lane & 3;

    const int bh = blockIdx.y;
    const int b = bh >> 4, h = bh & 15;
    const int kv = g_kvidx[h];
    const int q0 = blockIdx.x * 256;

    const __half* Qf = g_Qf + ((size_t)(b * Hc + h) * Pc + q0) * HDc;
    const __half* Kf = g_Kf + (size_t)(b * KVc + kv) * Pc * HDc;
    const __half* Vf = g_Vf + (size_t)(b * KVc + kv) * Pc * HDc;

    // KV loader: 256 threads, 64B each (K 8KB + V 8KB per chunk)
    const int lr = tid >> 2;            // 0..63
    const int lcb = (tid & 3) * 32;     // 0,32,64,96
    auto load_kv = [&](int chunk, uint32_t dst) {
        const size_t go = (size_t)(chunk * 64 + lr) * (HDc * 2) + lcb;
        const uint32_t so = dst + lr * FPB + lcb;
#pragma unroll
        for (int j = 0; j < 2; ++j) {
            CP_ASYNC16(so + j * 16,          (const char*)Kf + go + j * 16);
            CP_ASYNC16(so + TILE_H + j * 16, (const char*)Vf + go + j * 16);
        }
    };

    // stage Q: 256 rows (one per thread) across the whole smem region
    {
        const size_t go = (size_t)tid * (HDc * 2);
        const uint32_t so = sb + tid * FPB;
#pragma unroll
        for (int j = 0; j < 8; ++j)
            CP_ASYNC16(so + j * 16, (const char*)Qf + go + j * 16);
    }
    CP_COMMIT();
    CP_WAIT0();             // Q resident
    __syncthreads();

    // extract Q fragments: warp w owns q rows [w*32, w*32+32)
    uint32_t ah[2][4][4];
#pragma unroll
    for (int mt = 0; mt < 2; ++mt)
#pragma unroll
        for (int ks = 0; ks < 4; ++ks) {
            const uint32_t aq = sb + (w * 32 + mt * 16 + (lane & 15)) * FPB
                                + (ks * 16 + ((lane >> 4) & 1) * 8) * 2;
            ldm_x4(ah[mt][ks], aq);
        }
    __syncthreads();        // Q reads done; smem becomes the KV ring
    load_kv(0, sb);
    CP_COMMIT();            // g: KV0
    load_kv(1, sb + BUFH);
    CP_COMMIT();            // g: KV1

    const uint32_t b_ones[2] = { ONES_H2, ONES_H2 };
    float lacc[2][4];
    float o[2][8][4];
#pragma unroll
    for (int mt = 0; mt < 2; ++mt) {
#pragma unroll
        for (int c = 0; c < 4; c++) lacc[mt][c] = 0.f;
#pragma unroll
        for (int i = 0; i < 8; i++)
#pragma unroll
            for (int c = 0; c < 4; c++) o[mt][i][c] = 0.f;
    }

    for (int kt = 0; kt < Pc / 64; ++kt) {
        CP_WAIT1();
        __syncthreads();
        const uint32_t buf = sb + (kt & 1) * BUFH;

        // per-key-group fused pipeline (group = 16 keys)
#pragma unroll
        for (int ntp = 0; ntp < 4; ++ntp) {
            // S' for this group
            float sl[2][2][4];
#pragma unroll
            for (int mt = 0; mt < 2; ++mt)
#pragma unroll
                for (int i = 0; i < 2; ++i)
#pragma unroll
                    for (int c = 0; c < 4; ++c) sl[mt][i][c] = 0.f;
#pragma unroll
            for (int ks = 0; ks < 4; ++ks) {
                uint32_t k4[4];
                const uint32_t ab = buf
                    + (ntp * 16 + ((lane >> 4) << 3) + (lane & 7)) * FPB
                    + (ks * 16 + ((lane >> 3) & 1) * 8) * 2;
                ldm_x4(k4, ab);
#pragma unroll
                for (int mt = 0; mt < 2; ++mt) {
                    mma_f16(sl[mt][0], ah[mt][ks], k4);
                    mma_f16(sl[mt][1], ah[mt][ks], k4 + 2);
                }
            }
            // P for this group (fp16 A fragments)
            uint32_t pg[2][4];
#pragma unroll
            for (int mt = 0; mt < 2; ++mt) {
                pg[mt][0] = exp2_h2(sl[mt][0][1], sl[mt][0][0]);
                pg[mt][1] = exp2_h2(sl[mt][0][3], sl[mt][0][2]);
                pg[mt][2] = exp2_h2(sl[mt][1][1], sl[mt][1][0]);
                pg[mt][3] = exp2_h2(sl[mt][1][3], sl[mt][1][2]);
                mma_f16(lacc[mt], pg[mt], b_ones);
            }
            // O += P_group @ V_group
#pragma unroll
            for (int dtp = 0; dtp < 4; ++dtp) {
                uint32_t v4[4];
                const uint32_t av = buf + TILE_H
                    + (ntp * 16 + ((lane >> 3) & 1) * 8 + (lane & 7)) * FPB
                    + (dtp * 16 + ((lane >> 4) & 1) * 8) * 2;
                ldm_x4t(v4, av);
#pragma unroll
                for (int mt = 0; mt < 2; ++mt) {
                    mma_f16(o[mt][dtp * 2],     pg[mt], v4);
                    mma_f16(o[mt][dtp * 2 + 1], pg[mt], v4 + 2);
                }
            }
        }
        __syncthreads();
        if (kt + 2 < Pc / 64) {
            load_kv(kt + 2, sb + (kt & 1) * BUFH);
            CP_COMMIT();
        }
    }

    // ---- epilogue: normalize, write fp16 into proj-GEMM A (g_Of) ----
#pragma unroll
    for (int mt = 0; mt < 2; ++mt) {
        const float inv0 = 1.f / lacc[mt][0], inv1 = 1.f / lacc[mt][2];
        const size_t rowbase = (size_t)(b * Pc + q0 + w * 32 + mt * 16);
#pragma unroll
        for (int dt = 0; dt < 8; ++dt) {
            const int col = h * HDc + dt * 8 + tig * 2;
            *(__half2*)&g_Of[(rowbase + gid) * DIMC + col] =
                __floats2half2_rn(o[mt][dt][0] * inv0, o[mt][dt][1] * inv0);
            *(__half2*)&g_Of[(rowbase + gid + 8) * DIMC + col] =
                __floats2half2_rn(o[mt][dt][2] * inv1, o[mt][dt][3] * inv1);
        }
    }
}

// ---------------------------------------------------------------------------
extern "C" void kernel_launch(void* const* d_in, const int* in_sizes, int n_in,
                              void* d_out, int out_size) {
    const float* x  = (const float*)d_in[0];
    const float* Wq = (const float*)d_in[1];
    const float* Wk = (const float*)d_in[2];
    const float* Wv = (const float*)d_in[3];
    const float* Wp = (const float*)d_in[4];
    const float* bp = (const float*)d_in[5];
    float* out = (float*)d_out;

    static bool init_done = false;
    static __half *pXf, *pWf, *pPf, *pOf;
    if (!init_done) {
        cudaFuncSetAttribute(gemm_f16, cudaFuncAttributeMaxDynamicSharedMemorySize, SMEM_G16);
        cudaFuncSetAttribute(flash_mma, cudaFuncAttributeMaxDynamicSharedMemorySize, SMEM_FLASH);
        cudaGetSymbolAddress((void**)&pXf, g_Xf);
        cudaGetSymbolAddress((void**)&pWf, g_Wf);
        cudaGetSymbolAddress((void**)&pPf, g_Pf);
        cudaGetSymbolAddress((void**)&pOf, g_Of);
        init_done = true;
    }

    // converts: x (one launch) + all four weight tensors (one launch)
    convert_f16<<<MROWS * KD / 1024, 256>>>(x, pXf, MROWS * KD);
    convert_weights<<<3072, 256>>>(Wq, Wk, Wv, Wp);

    // QKV projection (fp16 single-product) -> fp16 Q/K/V
    gemm_f16<<<dim3(NQKV / 128, MROWS / 128), 256, SMEM_G16>>>(
        pXf, pWf, nullptr, nullptr, 0);

    knorm_kernel<<<Bc * KVc * KN_SPLIT, 256>>>();
    alloc_kernel<<<1, 32>>>();

    // fp16 tensor-core flash attention -> fp16 attn output into g_Of
    flash_mma<<<dim3(Pc / 256, Bc * Hc), 256, SMEM_FLASH>>>();

    // output projection (fp16 single-product) + bias -> fp32 out
    gemm_f16<<<dim3(DIMC / 128, MROWS / 128), 256, SMEM_G16>>>(
        pOf, pPf, bp, out, 1);
}